// round 9
// baseline (speedup 1.0000x reference)
#include <cuda_runtime.h>
#include <math.h>

// Fused: conv3d(32->64, k=3, pad=1) + bias + maxpool(2,2,2) + logsumexp(ch) + relu
// x: [16,32,48,48,48]  w: [64,32,3,3,3]  b: [64]  out: [16,1,24,24,24]
//
// Grid: (216 tiles, 16 batches). Block: 512 threads = 64 pooled cells x 8 oc-groups.
// Each CTA computes an 8x8x8 conv tile (=4x4x4 pooled cells), all 64 channels,
// looping over 32 input channels with smem-staged input halo (10^3) + weights.
// Accumulation uses packed fp32x2 FMA (fma.rn.f32x2) over output-channel pairs.

#define IN_PY 12     // padded y-stride (floats)
#define IN_PZ 120    // padded z-stride (floats)

__global__ void __launch_bounds__(512, 1)
fused_conv_pool_lse_kernel(const float* __restrict__ x,
                           const float* __restrict__ w,
                           const float* __restrict__ b,
                           float* __restrict__ out)
{
    __shared__ __align__(16) float in_s[10 * IN_PZ];          // 10x10x10 halo, padded
    __shared__ __align__(16) float w_s[32 * 27 * 2];          // [oc_pair][k][half]
    __shared__ float b_s[64];
    __shared__ float red_max[64 * 8];
    __shared__ float red_sum[64 * 8];

    const int n  = blockIdx.y;
    const int t  = blockIdx.x;                 // 0..215
    const int tz = t / 36;
    const int ty = (t / 6) % 6;
    const int tx = t % 6;
    const int d0 = tz * 8, h0 = ty * 8, w0 = tx * 8;   // conv-tile origin

    const int tid  = threadIdx.x;
    const int cell = tid & 63;                 // pooled cell within 4x4x4
    const int ocg  = tid >> 6;                 // oc group 0..7 (8 oc each)
    const int cx = cell & 3, cy = (cell >> 2) & 3, cz = cell >> 4;

    if (tid < 64) b_s[tid] = b[tid];

    // acc[pos][pair]: pos = dz*4+dy*2+dx over the 2x2x2 pooling window,
    // pair = packed (oc0, oc1) fp32x2 accumulator.
    unsigned long long acc[8][4];
#pragma unroll
    for (int i = 0; i < 8; ++i)
#pragma unroll
        for (int j = 0; j < 4; ++j) acc[i][j] = 0ull;

    const float* xn = x + (size_t)n * 32 * 48 * 48 * 48;

    for (int ic = 0; ic < 32; ++ic) {
        __syncthreads();   // protect smem from previous iteration's readers

        // ---- stage input halo slice [d0-1 .. d0+8]^3 (zero padded) ----
        const float* xc = xn + (size_t)ic * 48 * 48 * 48;
#pragma unroll
        for (int i = 0; i < 2; ++i) {
            int idx = tid + i * 512;
            if (idx < 1000) {
                int zi  = idx / 100;
                int rem = idx - zi * 100;
                int yi  = rem / 10;
                int xi  = rem - yi * 10;
                int gz = d0 - 1 + zi, gy = h0 - 1 + yi, gx = w0 - 1 + xi;
                float v = 0.0f;
                if ((unsigned)gz < 48u && (unsigned)gy < 48u && (unsigned)gx < 48u)
                    v = xc[(gz * 48 + gy) * 48 + gx];
                in_s[zi * IN_PZ + yi * IN_PY + xi] = v;
            }
        }

        // ---- stage weights for this ic: 64 oc x 27, pair-interleaved ----
        const float* wc = w + (size_t)ic * 27;
#pragma unroll
        for (int i = 0; i < 4; ++i) {
            int idx = tid + i * 512;
            if (idx < 1728) {
                int oc = idx / 27;
                int k  = idx - oc * 27;
                float v = wc[(size_t)oc * (32 * 27) + k];
                w_s[((oc >> 1) * 27 + k) * 2 + (oc & 1)] = v;
            }
        }
        __syncthreads();

        // ---- accumulate ----
        const float* inb = in_s + (2 * cz) * IN_PZ + (2 * cy) * IN_PY + 2 * cx;
        const float* wb  = w_s + (ocg * 4) * 27 * 2;

#pragma unroll
        for (int kz = 0; kz < 3; ++kz) {
#pragma unroll
            for (int ky = 0; ky < 3; ++ky) {
                // hoist weight pairs for kx = 0..2 (warp-uniform -> smem broadcast)
                unsigned long long wq[3][4];
#pragma unroll
                for (int kx = 0; kx < 3; ++kx) {
                    const int k = (kz * 3 + ky) * 3 + kx;
#pragma unroll
                    for (int pr = 0; pr < 4; ++pr)
                        wq[kx][pr] = *(const unsigned long long*)(wb + (pr * 27 + k) * 2);
                }
#pragma unroll
                for (int dz = 0; dz < 2; ++dz) {
#pragma unroll
                    for (int dy = 0; dy < 2; ++dy) {
                        const float* row = inb + (dz + kz) * IN_PZ + (dy + ky) * IN_PY;
                        // 4 consecutive x values cover all kx+dx combinations
                        float2 v01 = *(const float2*)(row);
                        float2 v23 = *(const float2*)(row + 2);
                        float vv[4];
                        vv[0] = v01.x; vv[1] = v01.y; vv[2] = v23.x; vv[3] = v23.y;
                        unsigned long long pdup[4];
#pragma unroll
                        for (int q = 0; q < 4; ++q)
                            asm("mov.b64 %0, {%1, %1};"
                                : "=l"(pdup[q]) : "r"(__float_as_uint(vv[q])));
#pragma unroll
                        for (int kx = 0; kx < 3; ++kx) {
#pragma unroll
                            for (int dx = 0; dx < 2; ++dx) {
                                const int pos = dz * 4 + dy * 2 + dx;
#pragma unroll
                                for (int pr = 0; pr < 4; ++pr)
                                    asm("fma.rn.f32x2 %0, %1, %2, %0;"
                                        : "+l"(acc[pos][pr])
                                        : "l"(pdup[kx + dx]), "l"(wq[kx][pr]));
                            }
                        }
                    }
                }
            }
        }
    }

    // ---- epilogue: bias + maxpool (in registers) ----
    float m[8];
#pragma unroll
    for (int pr = 0; pr < 4; ++pr) {
        float m0 = -INFINITY, m1 = -INFINITY;
#pragma unroll
        for (int pos = 0; pos < 8; ++pos) {
            unsigned int lo, hi;
            asm("mov.b64 {%0, %1}, %2;" : "=r"(lo), "=r"(hi) : "l"(acc[pos][pr]));
            m0 = fmaxf(m0, __uint_as_float(lo));
            m1 = fmaxf(m1, __uint_as_float(hi));
        }
        const int oc0 = ocg * 8 + pr * 2;
        m[pr * 2]     = m0 + b_s[oc0];
        m[pr * 2 + 1] = m1 + b_s[oc0 + 1];
    }
    float mx = m[0];
#pragma unroll
    for (int i = 1; i < 8; ++i) mx = fmaxf(mx, m[i]);

    // ---- logsumexp across the 8 oc-groups of this cell ----
    __syncthreads();
    red_max[cell * 8 + ocg] = mx;
    __syncthreads();

    float M = red_max[cell * 8 + 0];
#pragma unroll
    for (int i = 1; i < 8; ++i) M = fmaxf(M, red_max[cell * 8 + i]);

    float s = 0.0f;
#pragma unroll
    for (int i = 0; i < 8; ++i) s += expf(m[i] - M);
    red_sum[cell * 8 + ocg] = s;
    __syncthreads();

    if (ocg == 0) {
        float S = 0.0f;
#pragma unroll
        for (int i = 0; i < 8; ++i) S += red_sum[cell * 8 + i];
        float lse = M + logf(S);
        lse = fmaxf(lse, 0.0f);
        const int pd = tz * 4 + cz;
        const int ph = ty * 4 + cy;
        const int pw = tx * 4 + cx;
        out[((n * 24 + pd) * 24 + ph) * 24 + pw] = lse;
    }
}

extern "C" void kernel_launch(void* const* d_in, const int* in_sizes, int n_in,
                              void* d_out, int out_size)
{
    const float* x = (const float*)d_in[0];
    const float* w = (const float*)d_in[1];
    const float* b = (const float*)d_in[2];
    float* out = (float*)d_out;

    dim3 grid(216, 16);   // 6*6*6 conv tiles per batch, 16 batches
    fused_conv_pool_lse_kernel<<<grid, 512>>>(x, w, b, out);
}

// round 10
// speedup vs baseline: 1.0003x; 1.0003x over previous
#include <cuda_runtime.h>
#include <math.h>

// Fused: conv3d(32->64, k=3, pad=1) + bias + maxpool(2,2,2) + logsumexp(ch) + relu
// x: [16,32,48,48,48]  w: [64,32,3,3,3]  b: [64]  out: [16,1,24,24,24]
//
// Grid: (216 tiles, 16 batches). Block: 512 threads = 64 pooled cells x 8 oc-groups.
// Each CTA computes an 8x8x8 conv tile (=4x4x4 pooled cells), all 64 channels,
// looping over 32 input channels with smem-staged input halo (10^3) + weights.
// Accumulation uses packed fp32x2 FMA (fma.rn.f32x2) over output-channel pairs.

#define IN_PY 12     // padded y-stride (floats)
#define IN_PZ 120    // padded z-stride (floats)

__global__ void __launch_bounds__(512, 1)
fused_conv_pool_lse_kernel(const float* __restrict__ x,
                           const float* __restrict__ w,
                           const float* __restrict__ b,
                           float* __restrict__ out)
{
    __shared__ __align__(16) float in_s[10 * IN_PZ];          // 10x10x10 halo, padded
    __shared__ __align__(16) float w_s[32 * 27 * 2];          // [oc_pair][k][half]
    __shared__ float b_s[64];
    __shared__ float red_max[64 * 8];
    __shared__ float red_sum[64 * 8];

    const int n  = blockIdx.y;
    const int t  = blockIdx.x;                 // 0..215
    const int tz = t / 36;
    const int ty = (t / 6) % 6;
    const int tx = t % 6;
    const int d0 = tz * 8, h0 = ty * 8, w0 = tx * 8;   // conv-tile origin

    const int tid  = threadIdx.x;
    const int cell = tid & 63;                 // pooled cell within 4x4x4
    const int ocg  = tid >> 6;                 // oc group 0..7 (8 oc each)
    const int cx = cell & 3, cy = (cell >> 2) & 3, cz = cell >> 4;

    if (tid < 64) b_s[tid] = b[tid];

    // acc[pos][pair]: pos = dz*4+dy*2+dx over the 2x2x2 pooling window,
    // pair = packed (oc0, oc1) fp32x2 accumulator.
    unsigned long long acc[8][4];
#pragma unroll
    for (int i = 0; i < 8; ++i)
#pragma unroll
        for (int j = 0; j < 4; ++j) acc[i][j] = 0ull;

    const float* xn = x + (size_t)n * 32 * 48 * 48 * 48;

    for (int ic = 0; ic < 32; ++ic) {
        __syncthreads();   // protect smem from previous iteration's readers

        // ---- stage input halo slice [d0-1 .. d0+8]^3 (zero padded) ----
        const float* xc = xn + (size_t)ic * 48 * 48 * 48;
#pragma unroll
        for (int i = 0; i < 2; ++i) {
            int idx = tid + i * 512;
            if (idx < 1000) {
                int zi  = idx / 100;
                int rem = idx - zi * 100;
                int yi  = rem / 10;
                int xi  = rem - yi * 10;
                int gz = d0 - 1 + zi, gy = h0 - 1 + yi, gx = w0 - 1 + xi;
                float v = 0.0f;
                if ((unsigned)gz < 48u && (unsigned)gy < 48u && (unsigned)gx < 48u)
                    v = xc[(gz * 48 + gy) * 48 + gx];
                in_s[zi * IN_PZ + yi * IN_PY + xi] = v;
            }
        }

        // ---- stage weights for this ic: 64 oc x 27, pair-interleaved ----
        const float* wc = w + (size_t)ic * 27;
#pragma unroll
        for (int i = 0; i < 4; ++i) {
            int idx = tid + i * 512;
            if (idx < 1728) {
                int oc = idx / 27;
                int k  = idx - oc * 27;
                float v = wc[(size_t)oc * (32 * 27) + k];
                w_s[((oc >> 1) * 27 + k) * 2 + (oc & 1)] = v;
            }
        }
        __syncthreads();

        // ---- accumulate ----
        const float* inb = in_s + (2 * cz) * IN_PZ + (2 * cy) * IN_PY + 2 * cx;
        const float* wb  = w_s + (ocg * 4) * 27 * 2;

#pragma unroll
        for (int kz = 0; kz < 3; ++kz) {
#pragma unroll
            for (int ky = 0; ky < 3; ++ky) {
                // hoist weight pairs for kx = 0..2 (warp-uniform -> smem broadcast)
                unsigned long long wq[3][4];
#pragma unroll
                for (int kx = 0; kx < 3; ++kx) {
                    const int k = (kz * 3 + ky) * 3 + kx;
#pragma unroll
                    for (int pr = 0; pr < 4; ++pr)
                        wq[kx][pr] = *(const unsigned long long*)(wb + (pr * 27 + k) * 2);
                }
#pragma unroll
                for (int dz = 0; dz < 2; ++dz) {
#pragma unroll
                    for (int dy = 0; dy < 2; ++dy) {
                        const float* row = inb + (dz + kz) * IN_PZ + (dy + ky) * IN_PY;
                        // 4 consecutive x values cover all kx+dx combinations
                        float2 v01 = *(const float2*)(row);
                        float2 v23 = *(const float2*)(row + 2);
                        float vv[4];
                        vv[0] = v01.x; vv[1] = v01.y; vv[2] = v23.x; vv[3] = v23.y;
                        unsigned long long pdup[4];
#pragma unroll
                        for (int q = 0; q < 4; ++q)
                            asm("mov.b64 %0, {%1, %1};"
                                : "=l"(pdup[q]) : "r"(__float_as_uint(vv[q])));
#pragma unroll
                        for (int kx = 0; kx < 3; ++kx) {
#pragma unroll
                            for (int dx = 0; dx < 2; ++dx) {
                                const int pos = dz * 4 + dy * 2 + dx;
#pragma unroll
                                for (int pr = 0; pr < 4; ++pr)
                                    asm("fma.rn.f32x2 %0, %1, %2, %0;"
                                        : "+l"(acc[pos][pr])
                                        : "l"(pdup[kx + dx]), "l"(wq[kx][pr]));
                            }
                        }
                    }
                }
            }
        }
    }

    // ---- epilogue: bias + maxpool (in registers) ----
    float m[8];
#pragma unroll
    for (int pr = 0; pr < 4; ++pr) {
        float m0 = -INFINITY, m1 = -INFINITY;
#pragma unroll
        for (int pos = 0; pos < 8; ++pos) {
            unsigned int lo, hi;
            asm("mov.b64 {%0, %1}, %2;" : "=r"(lo), "=r"(hi) : "l"(acc[pos][pr]));
            m0 = fmaxf(m0, __uint_as_float(lo));
            m1 = fmaxf(m1, __uint_as_float(hi));
        }
        const int oc0 = ocg * 8 + pr * 2;
        m[pr * 2]     = m0 + b_s[oc0];
        m[pr * 2 + 1] = m1 + b_s[oc0 + 1];
    }
    float mx = m[0];
#pragma unroll
    for (int i = 1; i < 8; ++i) mx = fmaxf(mx, m[i]);

    // ---- logsumexp across the 8 oc-groups of this cell ----
    __syncthreads();
    red_max[cell * 8 + ocg] = mx;
    __syncthreads();

    float M = red_max[cell * 8 + 0];
#pragma unroll
    for (int i = 1; i < 8; ++i) M = fmaxf(M, red_max[cell * 8 + i]);

    float s = 0.0f;
#pragma unroll
    for (int i = 0; i < 8; ++i) s += expf(m[i] - M);
    red_sum[cell * 8 + ocg] = s;
    __syncthreads();

    if (ocg == 0) {
        float S = 0.0f;
#pragma unroll
        for (int i = 0; i < 8; ++i) S += red_sum[cell * 8 + i];
        float lse = M + logf(S);
        lse = fmaxf(lse, 0.0f);
        const int pd = tz * 4 + cz;
        const int ph = ty * 4 + cy;
        const int pw = tx * 4 + cx;
        out[((n * 24 + pd) * 24 + ph) * 24 + pw] = lse;
    }
}

extern "C" void kernel_launch(void* const* d_in, const int* in_sizes, int n_in,
                              void* d_out, int out_size)
{
    const float* x = (const float*)d_in[0];
    const float* w = (const float*)d_in[1];
    const float* b = (const float*)d_in[2];
    float* out = (float*)d_out;

    dim3 grid(216, 16);   // 6*6*6 conv tiles per batch, 16 batches
    fused_conv_pool_lse_kernel<<<grid, 512>>>(x, w, b, out);
}

// round 11
// speedup vs baseline: 1.0033x; 1.0030x over previous
#include <cuda_runtime.h>
#include <math.h>

// Fused: conv3d(32->64, k=3, pad=1) + bias + maxpool(2,2,2) + logsumexp(ch) + relu
// x: [16,32,48,48,48]  w: [64,32,3,3,3]  b: [64]  out: [16,1,24,24,24]
//
// Grid: (216 tiles, 16 batches). Block: 512 threads = 64 pooled cells x 8 oc-groups.
// Each CTA computes an 8x8x8 conv tile (=4x4x4 pooled cells), all 64 channels,
// looping over 32 input channels with smem-staged input halo (10^3) + weights.
// Accumulation uses packed fp32x2 FMA (fma.rn.f32x2) over output-channel pairs.

#define IN_PY 12     // padded y-stride (floats)
#define IN_PZ 120    // padded z-stride (floats)

__global__ void __launch_bounds__(512, 1)
fused_conv_pool_lse_kernel(const float* __restrict__ x,
                           const float* __restrict__ w,
                           const float* __restrict__ b,
                           float* __restrict__ out)
{
    __shared__ __align__(16) float in_s[10 * IN_PZ];          // 10x10x10 halo, padded
    __shared__ __align__(16) float w_s[32 * 27 * 2];          // [oc_pair][k][half]
    __shared__ float b_s[64];
    __shared__ float red_max[64 * 8];
    __shared__ float red_sum[64 * 8];

    const int n  = blockIdx.y;
    const int t  = blockIdx.x;                 // 0..215
    const int tz = t / 36;
    const int ty = (t / 6) % 6;
    const int tx = t % 6;
    const int d0 = tz * 8, h0 = ty * 8, w0 = tx * 8;   // conv-tile origin

    const int tid  = threadIdx.x;
    const int cell = tid & 63;                 // pooled cell within 4x4x4
    const int ocg  = tid >> 6;                 // oc group 0..7 (8 oc each)
    const int cx = cell & 3, cy = (cell >> 2) & 3, cz = cell >> 4;

    if (tid < 64) b_s[tid] = b[tid];

    // acc[pos][pair]: pos = dz*4+dy*2+dx over the 2x2x2 pooling window,
    // pair = packed (oc0, oc1) fp32x2 accumulator.
    unsigned long long acc[8][4];
#pragma unroll
    for (int i = 0; i < 8; ++i)
#pragma unroll
        for (int j = 0; j < 4; ++j) acc[i][j] = 0ull;

    const float* xn = x + (size_t)n * 32 * 48 * 48 * 48;

    for (int ic = 0; ic < 32; ++ic) {
        __syncthreads();   // protect smem from previous iteration's readers

        // ---- stage input halo slice [d0-1 .. d0+8]^3 (zero padded) ----
        const float* xc = xn + (size_t)ic * 48 * 48 * 48;
#pragma unroll
        for (int i = 0; i < 2; ++i) {
            int idx = tid + i * 512;
            if (idx < 1000) {
                int zi  = idx / 100;
                int rem = idx - zi * 100;
                int yi  = rem / 10;
                int xi  = rem - yi * 10;
                int gz = d0 - 1 + zi, gy = h0 - 1 + yi, gx = w0 - 1 + xi;
                float v = 0.0f;
                if ((unsigned)gz < 48u && (unsigned)gy < 48u && (unsigned)gx < 48u)
                    v = xc[(gz * 48 + gy) * 48 + gx];
                in_s[zi * IN_PZ + yi * IN_PY + xi] = v;
            }
        }

        // ---- stage weights for this ic: 64 oc x 27, pair-interleaved ----
        const float* wc = w + (size_t)ic * 27;
#pragma unroll
        for (int i = 0; i < 4; ++i) {
            int idx = tid + i * 512;
            if (idx < 1728) {
                int oc = idx / 27;
                int k  = idx - oc * 27;
                float v = wc[(size_t)oc * (32 * 27) + k];
                w_s[((oc >> 1) * 27 + k) * 2 + (oc & 1)] = v;
            }
        }
        __syncthreads();

        // ---- accumulate ----
        const float* inb = in_s + (2 * cz) * IN_PZ + (2 * cy) * IN_PY + 2 * cx;
        const float* wb  = w_s + (ocg * 4) * 27 * 2;

#pragma unroll
        for (int kz = 0; kz < 3; ++kz) {
#pragma unroll
            for (int ky = 0; ky < 3; ++ky) {
                // hoist weight pairs for kx = 0..2 (warp-uniform -> smem broadcast)
                unsigned long long wq[3][4];
#pragma unroll
                for (int kx = 0; kx < 3; ++kx) {
                    const int k = (kz * 3 + ky) * 3 + kx;
#pragma unroll
                    for (int pr = 0; pr < 4; ++pr)
                        wq[kx][pr] = *(const unsigned long long*)(wb + (pr * 27 + k) * 2);
                }
#pragma unroll
                for (int dz = 0; dz < 2; ++dz) {
#pragma unroll
                    for (int dy = 0; dy < 2; ++dy) {
                        const float* row = inb + (dz + kz) * IN_PZ + (dy + ky) * IN_PY;
                        // 4 consecutive x values cover all kx+dx combinations
                        float2 v01 = *(const float2*)(row);
                        float2 v23 = *(const float2*)(row + 2);
                        float vv[4];
                        vv[0] = v01.x; vv[1] = v01.y; vv[2] = v23.x; vv[3] = v23.y;
                        unsigned long long pdup[4];
#pragma unroll
                        for (int q = 0; q < 4; ++q)
                            asm("mov.b64 %0, {%1, %1};"
                                : "=l"(pdup[q]) : "r"(__float_as_uint(vv[q])));
#pragma unroll
                        for (int kx = 0; kx < 3; ++kx) {
#pragma unroll
                            for (int dx = 0; dx < 2; ++dx) {
                                const int pos = dz * 4 + dy * 2 + dx;
#pragma unroll
                                for (int pr = 0; pr < 4; ++pr)
                                    asm("fma.rn.f32x2 %0, %1, %2, %0;"
                                        : "+l"(acc[pos][pr])
                                        : "l"(pdup[kx + dx]), "l"(wq[kx][pr]));
                            }
                        }
                    }
                }
            }
        }
    }

    // ---- epilogue: bias + maxpool (in registers) ----
    float m[8];
#pragma unroll
    for (int pr = 0; pr < 4; ++pr) {
        float m0 = -INFINITY, m1 = -INFINITY;
#pragma unroll
        for (int pos = 0; pos < 8; ++pos) {
            unsigned int lo, hi;
            asm("mov.b64 {%0, %1}, %2;" : "=r"(lo), "=r"(hi) : "l"(acc[pos][pr]));
            m0 = fmaxf(m0, __uint_as_float(lo));
            m1 = fmaxf(m1, __uint_as_float(hi));
        }
        const int oc0 = ocg * 8 + pr * 2;
        m[pr * 2]     = m0 + b_s[oc0];
        m[pr * 2 + 1] = m1 + b_s[oc0 + 1];
    }
    float mx = m[0];
#pragma unroll
    for (int i = 1; i < 8; ++i) mx = fmaxf(mx, m[i]);

    // ---- logsumexp across the 8 oc-groups of this cell ----
    __syncthreads();
    red_max[cell * 8 + ocg] = mx;
    __syncthreads();

    float M = red_max[cell * 8 + 0];
#pragma unroll
    for (int i = 1; i < 8; ++i) M = fmaxf(M, red_max[cell * 8 + i]);

    float s = 0.0f;
#pragma unroll
    for (int i = 0; i < 8; ++i) s += expf(m[i] - M);
    red_sum[cell * 8 + ocg] = s;
    __syncthreads();

    if (ocg == 0) {
        float S = 0.0f;
#pragma unroll
        for (int i = 0; i < 8; ++i) S += red_sum[cell * 8 + i];
        float lse = M + logf(S);
        lse = fmaxf(lse, 0.0f);
        const int pd = tz * 4 + cz;
        const int ph = ty * 4 + cy;
        const int pw = tx * 4 + cx;
        out[((n * 24 + pd) * 24 + ph) * 24 + pw] = lse;
    }
}

extern "C" void kernel_launch(void* const* d_in, const int* in_sizes, int n_in,
                              void* d_out, int out_size)
{
    const float* x = (const float*)d_in[0];
    const float* w = (const float*)d_in[1];
    const float* b = (const float*)d_in[2];
    float* out = (float*)d_out;

    dim3 grid(216, 16);   // 6*6*6 conv tiles per batch, 16 batches
    fused_conv_pool_lse_kernel<<<grid, 512>>>(x, w, b, out);
}

// round 12
// speedup vs baseline: 1.1006x; 1.0970x over previous
#include <cuda_runtime.h>
#include <math.h>

// Fused: conv3d(32->64, k=3, pad=1) + bias + maxpool(2,2,2) + logsumexp(ch) + relu
// x: [16,32,48,48,48]  w: [64,32,3,3,3]  b: [64]  out: [16,1,24,24,24]
//
// Grid: (216 tiles, 16 batches). Block: 512 threads = 64 pooled cells x 8 oc-groups.
// Each CTA computes an 8x8x8 conv tile (=4x4x4 pooled cells), all 64 channels,
// looping over 32 input channels. Double-buffered smem staging: ic+1's halo and
// weights are prefetched into registers while ic computes, so LDG latency is
// hidden and only ONE __syncthreads per ic remains.
// Accumulation uses packed fp32x2 FMA (fma.rn.f32x2) over output-channel pairs.

#define IN_PY 12     // padded y-stride (floats)
#define IN_PZ 120    // padded z-stride (floats)
#define CH_STRIDE (48 * 48 * 48)

__global__ void __launch_bounds__(512, 1)
fused_conv_pool_lse_kernel(const float* __restrict__ x,
                           const float* __restrict__ w,
                           const float* __restrict__ b,
                           float* __restrict__ out)
{
    __shared__ __align__(16) float in_s[2][10 * IN_PZ];   // 10x10x10 halo, padded
    __shared__ __align__(16) float w_s[2][32 * 27 * 2];   // [oc_pair][k][half]
    __shared__ float b_s[64];
    __shared__ float red_max[64 * 8];
    __shared__ float red_sum[64 * 8];

    const int n  = blockIdx.y;
    const int t  = blockIdx.x;                 // 0..215
    const int tz = t / 36;
    const int ty = (t / 6) % 6;
    const int tx = t % 6;
    const int d0 = tz * 8, h0 = ty * 8, w0 = tx * 8;   // conv-tile origin

    const int tid  = threadIdx.x;
    const int cell = tid & 63;                 // pooled cell within 4x4x4
    const int ocg  = tid >> 6;                 // oc group 0..7 (8 oc each)
    const int cx = cell & 3, cy = (cell >> 2) & 3, cz = cell >> 4;

    if (tid < 64) b_s[tid] = b[tid];

    // ---- ic-invariant staging geometry (hoisted out of the main loop) ----
    // Input halo: element i covers idx = tid + i*512 (1000 total).
    int  xs_off[2];            // smem offset
    int  xg_off[2];            // gmem offset within one channel slab
    bool x_ok[2];              // in-bounds (else zero-fill)
    bool x_act[2];             // this thread participates
#pragma unroll
    for (int i = 0; i < 2; ++i) {
        int idx = tid + i * 512;
        x_act[i] = (idx < 1000);
        int zi  = idx / 100;
        int rem = idx - zi * 100;
        int yi  = rem / 10;
        int xi  = rem - yi * 10;
        int gz = d0 - 1 + zi, gy = h0 - 1 + yi, gx = w0 - 1 + xi;
        x_ok[i]   = ((unsigned)gz < 48u) & ((unsigned)gy < 48u) & ((unsigned)gx < 48u);
        xg_off[i] = (gz * 48 + gy) * 48 + gx;
        xs_off[i] = zi * IN_PZ + yi * IN_PY + xi;
    }
    // Weights: element j covers idx = tid + j*512 (1728 total), pair-interleaved smem.
    int  wg_off[4];
    int  ws_off[4];
    bool w_act[4];
#pragma unroll
    for (int j = 0; j < 4; ++j) {
        int idx = tid + j * 512;
        w_act[j] = (idx < 1728);
        int oc = idx / 27;
        int k  = idx - oc * 27;
        wg_off[j] = oc * (32 * 27) + k;                 // + ic*27 at load time
        ws_off[j] = ((oc >> 1) * 27 + k) * 2 + (oc & 1);
    }

    const float* xn = x + (size_t)n * 32 * CH_STRIDE;

    // ---- prefetch ic = 0 into registers ----
    float xr[2], wr[4];
#pragma unroll
    for (int i = 0; i < 2; ++i)
        xr[i] = (x_act[i] && x_ok[i]) ? __ldg(xn + xg_off[i]) : 0.0f;
#pragma unroll
    for (int j = 0; j < 4; ++j)
        wr[j] = w_act[j] ? __ldg(w + wg_off[j]) : 0.0f;

    // acc[pos][pair]: pos = dz*4+dy*2+dx over the 2x2x2 pooling window,
    // pair = packed (oc0, oc1) fp32x2 accumulator.
    unsigned long long acc[8][4];
#pragma unroll
    for (int i = 0; i < 8; ++i)
#pragma unroll
        for (int j = 0; j < 4; ++j) acc[i][j] = 0ull;

    for (int ic = 0; ic < 32; ++ic) {
        const int p = ic & 1;

        // ---- commit prefetched registers to smem buffer p ----
#pragma unroll
        for (int i = 0; i < 2; ++i)
            if (x_act[i]) in_s[p][xs_off[i]] = xr[i];
#pragma unroll
        for (int j = 0; j < 4; ++j)
            if (w_act[j]) w_s[p][ws_off[j]] = wr[j];
        __syncthreads();

        // ---- prefetch ic+1 (LDG in flight for the whole compute phase) ----
        if (ic < 31) {
            const float* xc = xn + (size_t)(ic + 1) * CH_STRIDE;
            const float* wc = w + (ic + 1) * 27;
#pragma unroll
            for (int i = 0; i < 2; ++i)
                xr[i] = (x_act[i] && x_ok[i]) ? __ldg(xc + xg_off[i]) : 0.0f;
#pragma unroll
            for (int j = 0; j < 4; ++j)
                wr[j] = w_act[j] ? __ldg(wc + wg_off[j]) : 0.0f;
        }

        // ---- accumulate from buffer p ----
        const float* inb = in_s[p] + (2 * cz) * IN_PZ + (2 * cy) * IN_PY + 2 * cx;
        const float* wb  = w_s[p] + (ocg * 4) * 27 * 2;

#pragma unroll
        for (int kz = 0; kz < 3; ++kz) {
#pragma unroll
            for (int ky = 0; ky < 3; ++ky) {
                // hoist weight pairs for kx = 0..2 (warp-uniform -> smem broadcast)
                unsigned long long wq[3][4];
#pragma unroll
                for (int kx = 0; kx < 3; ++kx) {
                    const int k = (kz * 3 + ky) * 3 + kx;
#pragma unroll
                    for (int pr = 0; pr < 4; ++pr)
                        wq[kx][pr] = *(const unsigned long long*)(wb + (pr * 27 + k) * 2);
                }
#pragma unroll
                for (int dz = 0; dz < 2; ++dz) {
#pragma unroll
                    for (int dy = 0; dy < 2; ++dy) {
                        const float* row = inb + (dz + kz) * IN_PZ + (dy + ky) * IN_PY;
                        // 4 consecutive x values cover all kx+dx combinations
                        float2 v01 = *(const float2*)(row);
                        float2 v23 = *(const float2*)(row + 2);
                        float vv[4];
                        vv[0] = v01.x; vv[1] = v01.y; vv[2] = v23.x; vv[3] = v23.y;
                        unsigned long long pdup[4];
#pragma unroll
                        for (int q = 0; q < 4; ++q)
                            asm("mov.b64 %0, {%1, %1};"
                                : "=l"(pdup[q]) : "r"(__float_as_uint(vv[q])));
#pragma unroll
                        for (int kx = 0; kx < 3; ++kx) {
#pragma unroll
                            for (int dx = 0; dx < 2; ++dx) {
                                const int pos = dz * 4 + dy * 2 + dx;
#pragma unroll
                                for (int pr = 0; pr < 4; ++pr)
                                    asm("fma.rn.f32x2 %0, %1, %2, %0;"
                                        : "+l"(acc[pos][pr])
                                        : "l"(pdup[kx + dx]), "l"(wq[kx][pr]));
                            }
                        }
                    }
                }
            }
        }
    }

    // ---- epilogue: bias + maxpool (in registers) ----
    float m[8];
#pragma unroll
    for (int pr = 0; pr < 4; ++pr) {
        float m0 = -INFINITY, m1 = -INFINITY;
#pragma unroll
        for (int pos = 0; pos < 8; ++pos) {
            unsigned int lo, hi;
            asm("mov.b64 {%0, %1}, %2;" : "=r"(lo), "=r"(hi) : "l"(acc[pos][pr]));
            m0 = fmaxf(m0, __uint_as_float(lo));
            m1 = fmaxf(m1, __uint_as_float(hi));
        }
        const int oc0 = ocg * 8 + pr * 2;
        m[pr * 2]     = m0 + b_s[oc0];
        m[pr * 2 + 1] = m1 + b_s[oc0 + 1];
    }
    float mx = m[0];
#pragma unroll
    for (int i = 1; i < 8; ++i) mx = fmaxf(mx, m[i]);

    // ---- logsumexp across the 8 oc-groups of this cell ----
    __syncthreads();
    red_max[cell * 8 + ocg] = mx;
    __syncthreads();

    float M = red_max[cell * 8 + 0];
#pragma unroll
    for (int i = 1; i < 8; ++i) M = fmaxf(M, red_max[cell * 8 + i]);

    float s = 0.0f;
#pragma unroll
    for (int i = 0; i < 8; ++i) s += expf(m[i] - M);
    red_sum[cell * 8 + ocg] = s;
    __syncthreads();

    if (ocg == 0) {
        float S = 0.0f;
#pragma unroll
        for (int i = 0; i < 8; ++i) S += red_sum[cell * 8 + i];
        float lse = M + logf(S);
        lse = fmaxf(lse, 0.0f);
        const int pd = tz * 4 + cz;
        const int ph = ty * 4 + cy;
        const int pw = tx * 4 + cx;
        out[((n * 24 + pd) * 24 + ph) * 24 + pw] = lse;
    }
}

extern "C" void kernel_launch(void* const* d_in, const int* in_sizes, int n_in,
                              void* d_out, int out_size)
{
    const float* x = (const float*)d_in[0];
    const float* w = (const float*)d_in[1];
    const float* b = (const float*)d_in[2];
    float* out = (float*)d_out;

    dim3 grid(216, 16);   // 6*6*6 conv tiles per batch, 16 batches
    fused_conv_pool_lse_kernel<<<grid, 512>>>(x, w, b, out);
}

// round 13
// speedup vs baseline: 1.1025x; 1.0017x over previous
#include <cuda_runtime.h>
#include <math.h>

// Fused: conv3d(32->64, k=3, pad=1) + bias + maxpool(2,2,2) + logsumexp(ch) + relu
// x: [16,32,48,48,48]  w: [64,32,3,3,3]  b: [64]  out: [16,1,24,24,24]
//
// Grid: (216 tiles, 16 batches). Block: 512 threads = 64 pooled cells x 8 oc-groups.
// Each CTA computes an 8x8x8 conv tile (=4x4x4 pooled cells), all 64 channels,
// looping over 32 input channels. Double-buffered smem staging: ic+1's halo and
// weights are prefetched into registers while ic computes, so LDG latency is
// hidden and only ONE __syncthreads per ic remains.
// Accumulation uses packed fp32x2 FMA (fma.rn.f32x2) over output-channel pairs.

#define IN_PY 12     // padded y-stride (floats)
#define IN_PZ 120    // padded z-stride (floats)
#define CH_STRIDE (48 * 48 * 48)

__global__ void __launch_bounds__(512, 1)
fused_conv_pool_lse_kernel(const float* __restrict__ x,
                           const float* __restrict__ w,
                           const float* __restrict__ b,
                           float* __restrict__ out)
{
    __shared__ __align__(16) float in_s[2][10 * IN_PZ];   // 10x10x10 halo, padded
    __shared__ __align__(16) float w_s[2][32 * 27 * 2];   // [oc_pair][k][half]
    __shared__ float b_s[64];
    __shared__ float red_max[64 * 8];
    __shared__ float red_sum[64 * 8];

    const int n  = blockIdx.y;
    const int t  = blockIdx.x;                 // 0..215
    const int tz = t / 36;
    const int ty = (t / 6) % 6;
    const int tx = t % 6;
    const int d0 = tz * 8, h0 = ty * 8, w0 = tx * 8;   // conv-tile origin

    const int tid  = threadIdx.x;
    const int cell = tid & 63;                 // pooled cell within 4x4x4
    const int ocg  = tid >> 6;                 // oc group 0..7 (8 oc each)
    const int cx = cell & 3, cy = (cell >> 2) & 3, cz = cell >> 4;

    if (tid < 64) b_s[tid] = b[tid];

    // ---- ic-invariant staging geometry (hoisted out of the main loop) ----
    // Input halo: element i covers idx = tid + i*512 (1000 total).
    int  xs_off[2];            // smem offset
    int  xg_off[2];            // gmem offset within one channel slab
    bool x_ok[2];              // in-bounds (else zero-fill)
    bool x_act[2];             // this thread participates
#pragma unroll
    for (int i = 0; i < 2; ++i) {
        int idx = tid + i * 512;
        x_act[i] = (idx < 1000);
        int zi  = idx / 100;
        int rem = idx - zi * 100;
        int yi  = rem / 10;
        int xi  = rem - yi * 10;
        int gz = d0 - 1 + zi, gy = h0 - 1 + yi, gx = w0 - 1 + xi;
        x_ok[i]   = ((unsigned)gz < 48u) & ((unsigned)gy < 48u) & ((unsigned)gx < 48u);
        xg_off[i] = (gz * 48 + gy) * 48 + gx;
        xs_off[i] = zi * IN_PZ + yi * IN_PY + xi;
    }
    // Weights: element j covers idx = tid + j*512 (1728 total), pair-interleaved smem.
    int  wg_off[4];
    int  ws_off[4];
    bool w_act[4];
#pragma unroll
    for (int j = 0; j < 4; ++j) {
        int idx = tid + j * 512;
        w_act[j] = (idx < 1728);
        int oc = idx / 27;
        int k  = idx - oc * 27;
        wg_off[j] = oc * (32 * 27) + k;                 // + ic*27 at load time
        ws_off[j] = ((oc >> 1) * 27 + k) * 2 + (oc & 1);
    }

    const float* xn = x + (size_t)n * 32 * CH_STRIDE;

    // ---- prefetch ic = 0 into registers ----
    float xr[2], wr[4];
#pragma unroll
    for (int i = 0; i < 2; ++i)
        xr[i] = (x_act[i] && x_ok[i]) ? __ldg(xn + xg_off[i]) : 0.0f;
#pragma unroll
    for (int j = 0; j < 4; ++j)
        wr[j] = w_act[j] ? __ldg(w + wg_off[j]) : 0.0f;

    // acc[pos][pair]: pos = dz*4+dy*2+dx over the 2x2x2 pooling window,
    // pair = packed (oc0, oc1) fp32x2 accumulator.
    unsigned long long acc[8][4];
#pragma unroll
    for (int i = 0; i < 8; ++i)
#pragma unroll
        for (int j = 0; j < 4; ++j) acc[i][j] = 0ull;

    for (int ic = 0; ic < 32; ++ic) {
        const int p = ic & 1;

        // ---- commit prefetched registers to smem buffer p ----
#pragma unroll
        for (int i = 0; i < 2; ++i)
            if (x_act[i]) in_s[p][xs_off[i]] = xr[i];
#pragma unroll
        for (int j = 0; j < 4; ++j)
            if (w_act[j]) w_s[p][ws_off[j]] = wr[j];
        __syncthreads();

        // ---- prefetch ic+1 (LDG in flight for the whole compute phase) ----
        if (ic < 31) {
            const float* xc = xn + (size_t)(ic + 1) * CH_STRIDE;
            const float* wc = w + (ic + 1) * 27;
#pragma unroll
            for (int i = 0; i < 2; ++i)
                xr[i] = (x_act[i] && x_ok[i]) ? __ldg(xc + xg_off[i]) : 0.0f;
#pragma unroll
            for (int j = 0; j < 4; ++j)
                wr[j] = w_act[j] ? __ldg(wc + wg_off[j]) : 0.0f;
        }

        // ---- accumulate from buffer p ----
        const float* inb = in_s[p] + (2 * cz) * IN_PZ + (2 * cy) * IN_PY + 2 * cx;
        const float* wb  = w_s[p] + (ocg * 4) * 27 * 2;

#pragma unroll
        for (int kz = 0; kz < 3; ++kz) {
#pragma unroll
            for (int ky = 0; ky < 3; ++ky) {
                // hoist weight pairs for kx = 0..2 (warp-uniform -> smem broadcast)
                unsigned long long wq[3][4];
#pragma unroll
                for (int kx = 0; kx < 3; ++kx) {
                    const int k = (kz * 3 + ky) * 3 + kx;
#pragma unroll
                    for (int pr = 0; pr < 4; ++pr)
                        wq[kx][pr] = *(const unsigned long long*)(wb + (pr * 27 + k) * 2);
                }
#pragma unroll
                for (int dz = 0; dz < 2; ++dz) {
#pragma unroll
                    for (int dy = 0; dy < 2; ++dy) {
                        const float* row = inb + (dz + kz) * IN_PZ + (dy + ky) * IN_PY;
                        // 4 consecutive x values cover all kx+dx combinations
                        float2 v01 = *(const float2*)(row);
                        float2 v23 = *(const float2*)(row + 2);
                        float vv[4];
                        vv[0] = v01.x; vv[1] = v01.y; vv[2] = v23.x; vv[3] = v23.y;
                        unsigned long long pdup[4];
#pragma unroll
                        for (int q = 0; q < 4; ++q)
                            asm("mov.b64 %0, {%1, %1};"
                                : "=l"(pdup[q]) : "r"(__float_as_uint(vv[q])));
#pragma unroll
                        for (int kx = 0; kx < 3; ++kx) {
#pragma unroll
                            for (int dx = 0; dx < 2; ++dx) {
                                const int pos = dz * 4 + dy * 2 + dx;
#pragma unroll
                                for (int pr = 0; pr < 4; ++pr)
                                    asm("fma.rn.f32x2 %0, %1, %2, %0;"
                                        : "+l"(acc[pos][pr])
                                        : "l"(pdup[kx + dx]), "l"(wq[kx][pr]));
                            }
                        }
                    }
                }
            }
        }
    }

    // ---- epilogue: bias + maxpool (in registers) ----
    float m[8];
#pragma unroll
    for (int pr = 0; pr < 4; ++pr) {
        float m0 = -INFINITY, m1 = -INFINITY;
#pragma unroll
        for (int pos = 0; pos < 8; ++pos) {
            unsigned int lo, hi;
            asm("mov.b64 {%0, %1}, %2;" : "=r"(lo), "=r"(hi) : "l"(acc[pos][pr]));
            m0 = fmaxf(m0, __uint_as_float(lo));
            m1 = fmaxf(m1, __uint_as_float(hi));
        }
        const int oc0 = ocg * 8 + pr * 2;
        m[pr * 2]     = m0 + b_s[oc0];
        m[pr * 2 + 1] = m1 + b_s[oc0 + 1];
    }
    float mx = m[0];
#pragma unroll
    for (int i = 1; i < 8; ++i) mx = fmaxf(mx, m[i]);

    // ---- logsumexp across the 8 oc-groups of this cell ----
    __syncthreads();
    red_max[cell * 8 + ocg] = mx;
    __syncthreads();

    float M = red_max[cell * 8 + 0];
#pragma unroll
    for (int i = 1; i < 8; ++i) M = fmaxf(M, red_max[cell * 8 + i]);

    float s = 0.0f;
#pragma unroll
    for (int i = 0; i < 8; ++i) s += expf(m[i] - M);
    red_sum[cell * 8 + ocg] = s;
    __syncthreads();

    if (ocg == 0) {
        float S = 0.0f;
#pragma unroll
        for (int i = 0; i < 8; ++i) S += red_sum[cell * 8 + i];
        float lse = M + logf(S);
        lse = fmaxf(lse, 0.0f);
        const int pd = tz * 4 + cz;
        const int ph = ty * 4 + cy;
        const int pw = tx * 4 + cx;
        out[((n * 24 + pd) * 24 + ph) * 24 + pw] = lse;
    }
}

extern "C" void kernel_launch(void* const* d_in, const int* in_sizes, int n_in,
                              void* d_out, int out_size)
{
    const float* x = (const float*)d_in[0];
    const float* w = (const float*)d_in[1];
    const float* b = (const float*)d_in[2];
    float* out = (float*)d_out;

    dim3 grid(216, 16);   // 6*6*6 conv tiles per batch, 16 batches
    fused_conv_pool_lse_kernel<<<grid, 512>>>(x, w, b, out);
}

// round 14
// speedup vs baseline: 1.1031x; 1.0006x over previous
#include <cuda_runtime.h>
#include <math.h>

// Fused: conv3d(32->64, k=3, pad=1) + bias + maxpool(2,2,2) + logsumexp(ch) + relu
// x: [16,32,48,48,48]  w: [64,32,3,3,3]  b: [64]  out: [16,1,24,24,24]
//
// Grid: (216 tiles, 16 batches). Block: 512 threads = 64 pooled cells x 8 oc-groups.
// Each CTA computes an 8x8x8 conv tile (=4x4x4 pooled cells), all 64 channels,
// looping over 32 input channels. Double-buffered smem staging: ic+1's halo and
// weights are prefetched into registers while ic computes, so LDG latency is
// hidden and only ONE __syncthreads per ic remains.
// Accumulation uses packed fp32x2 FMA (fma.rn.f32x2) over output-channel pairs.

#define IN_PY 12     // padded y-stride (floats)
#define IN_PZ 120    // padded z-stride (floats)
#define CH_STRIDE (48 * 48 * 48)

__global__ void __launch_bounds__(512, 1)
fused_conv_pool_lse_kernel(const float* __restrict__ x,
                           const float* __restrict__ w,
                           const float* __restrict__ b,
                           float* __restrict__ out)
{
    __shared__ __align__(16) float in_s[2][10 * IN_PZ];   // 10x10x10 halo, padded
    __shared__ __align__(16) float w_s[2][32 * 27 * 2];   // [oc_pair][k][half]
    __shared__ float b_s[64];
    __shared__ float red_max[64 * 8];
    __shared__ float red_sum[64 * 8];

    const int n  = blockIdx.y;
    const int t  = blockIdx.x;                 // 0..215
    const int tz = t / 36;
    const int ty = (t / 6) % 6;
    const int tx = t % 6;
    const int d0 = tz * 8, h0 = ty * 8, w0 = tx * 8;   // conv-tile origin

    const int tid  = threadIdx.x;
    const int cell = tid & 63;                 // pooled cell within 4x4x4
    const int ocg  = tid >> 6;                 // oc group 0..7 (8 oc each)
    const int cx = cell & 3, cy = (cell >> 2) & 3, cz = cell >> 4;

    if (tid < 64) b_s[tid] = b[tid];

    // ---- ic-invariant staging geometry (hoisted out of the main loop) ----
    // Input halo: element i covers idx = tid + i*512 (1000 total).
    int  xs_off[2];            // smem offset
    int  xg_off[2];            // gmem offset within one channel slab
    bool x_ok[2];              // in-bounds (else zero-fill)
    bool x_act[2];             // this thread participates
#pragma unroll
    for (int i = 0; i < 2; ++i) {
        int idx = tid + i * 512;
        x_act[i] = (idx < 1000);
        int zi  = idx / 100;
        int rem = idx - zi * 100;
        int yi  = rem / 10;
        int xi  = rem - yi * 10;
        int gz = d0 - 1 + zi, gy = h0 - 1 + yi, gx = w0 - 1 + xi;
        x_ok[i]   = ((unsigned)gz < 48u) & ((unsigned)gy < 48u) & ((unsigned)gx < 48u);
        xg_off[i] = (gz * 48 + gy) * 48 + gx;
        xs_off[i] = zi * IN_PZ + yi * IN_PY + xi;
    }
    // Weights: element j covers idx = tid + j*512 (1728 total), pair-interleaved smem.
    int  wg_off[4];
    int  ws_off[4];
    bool w_act[4];
#pragma unroll
    for (int j = 0; j < 4; ++j) {
        int idx = tid + j * 512;
        w_act[j] = (idx < 1728);
        int oc = idx / 27;
        int k  = idx - oc * 27;
        wg_off[j] = oc * (32 * 27) + k;                 // + ic*27 at load time
        ws_off[j] = ((oc >> 1) * 27 + k) * 2 + (oc & 1);
    }

    const float* xn = x + (size_t)n * 32 * CH_STRIDE;

    // ---- prefetch ic = 0 into registers ----
    float xr[2], wr[4];
#pragma unroll
    for (int i = 0; i < 2; ++i)
        xr[i] = (x_act[i] && x_ok[i]) ? __ldg(xn + xg_off[i]) : 0.0f;
#pragma unroll
    for (int j = 0; j < 4; ++j)
        wr[j] = w_act[j] ? __ldg(w + wg_off[j]) : 0.0f;

    // acc[pos][pair]: pos = dz*4+dy*2+dx over the 2x2x2 pooling window,
    // pair = packed (oc0, oc1) fp32x2 accumulator.
    unsigned long long acc[8][4];
#pragma unroll
    for (int i = 0; i < 8; ++i)
#pragma unroll
        for (int j = 0; j < 4; ++j) acc[i][j] = 0ull;

    for (int ic = 0; ic < 32; ++ic) {
        const int p = ic & 1;

        // ---- commit prefetched registers to smem buffer p ----
#pragma unroll
        for (int i = 0; i < 2; ++i)
            if (x_act[i]) in_s[p][xs_off[i]] = xr[i];
#pragma unroll
        for (int j = 0; j < 4; ++j)
            if (w_act[j]) w_s[p][ws_off[j]] = wr[j];
        __syncthreads();

        // ---- prefetch ic+1 (LDG in flight for the whole compute phase) ----
        if (ic < 31) {
            const float* xc = xn + (size_t)(ic + 1) * CH_STRIDE;
            const float* wc = w + (ic + 1) * 27;
#pragma unroll
            for (int i = 0; i < 2; ++i)
                xr[i] = (x_act[i] && x_ok[i]) ? __ldg(xc + xg_off[i]) : 0.0f;
#pragma unroll
            for (int j = 0; j < 4; ++j)
                wr[j] = w_act[j] ? __ldg(wc + wg_off[j]) : 0.0f;
        }

        // ---- accumulate from buffer p ----
        const float* inb = in_s[p] + (2 * cz) * IN_PZ + (2 * cy) * IN_PY + 2 * cx;
        const float* wb  = w_s[p] + (ocg * 4) * 27 * 2;

#pragma unroll
        for (int kz = 0; kz < 3; ++kz) {
#pragma unroll
            for (int ky = 0; ky < 3; ++ky) {
                // hoist weight pairs for kx = 0..2 (warp-uniform -> smem broadcast)
                unsigned long long wq[3][4];
#pragma unroll
                for (int kx = 0; kx < 3; ++kx) {
                    const int k = (kz * 3 + ky) * 3 + kx;
#pragma unroll
                    for (int pr = 0; pr < 4; ++pr)
                        wq[kx][pr] = *(const unsigned long long*)(wb + (pr * 27 + k) * 2);
                }
#pragma unroll
                for (int dz = 0; dz < 2; ++dz) {
#pragma unroll
                    for (int dy = 0; dy < 2; ++dy) {
                        const float* row = inb + (dz + kz) * IN_PZ + (dy + ky) * IN_PY;
                        // 4 consecutive x values cover all kx+dx combinations
                        float2 v01 = *(const float2*)(row);
                        float2 v23 = *(const float2*)(row + 2);
                        float vv[4];
                        vv[0] = v01.x; vv[1] = v01.y; vv[2] = v23.x; vv[3] = v23.y;
                        unsigned long long pdup[4];
#pragma unroll
                        for (int q = 0; q < 4; ++q)
                            asm("mov.b64 %0, {%1, %1};"
                                : "=l"(pdup[q]) : "r"(__float_as_uint(vv[q])));
#pragma unroll
                        for (int kx = 0; kx < 3; ++kx) {
#pragma unroll
                            for (int dx = 0; dx < 2; ++dx) {
                                const int pos = dz * 4 + dy * 2 + dx;
#pragma unroll
                                for (int pr = 0; pr < 4; ++pr)
                                    asm("fma.rn.f32x2 %0, %1, %2, %0;"
                                        : "+l"(acc[pos][pr])
                                        : "l"(pdup[kx + dx]), "l"(wq[kx][pr]));
                            }
                        }
                    }
                }
            }
        }
    }

    // ---- epilogue: bias + maxpool (in registers) ----
    float m[8];
#pragma unroll
    for (int pr = 0; pr < 4; ++pr) {
        float m0 = -INFINITY, m1 = -INFINITY;
#pragma unroll
        for (int pos = 0; pos < 8; ++pos) {
            unsigned int lo, hi;
            asm("mov.b64 {%0, %1}, %2;" : "=r"(lo), "=r"(hi) : "l"(acc[pos][pr]));
            m0 = fmaxf(m0, __uint_as_float(lo));
            m1 = fmaxf(m1, __uint_as_float(hi));
        }
        const int oc0 = ocg * 8 + pr * 2;
        m[pr * 2]     = m0 + b_s[oc0];
        m[pr * 2 + 1] = m1 + b_s[oc0 + 1];
    }
    float mx = m[0];
#pragma unroll
    for (int i = 1; i < 8; ++i) mx = fmaxf(mx, m[i]);

    // ---- logsumexp across the 8 oc-groups of this cell ----
    __syncthreads();
    red_max[cell * 8 + ocg] = mx;
    __syncthreads();

    float M = red_max[cell * 8 + 0];
#pragma unroll
    for (int i = 1; i < 8; ++i) M = fmaxf(M, red_max[cell * 8 + i]);

    float s = 0.0f;
#pragma unroll
    for (int i = 0; i < 8; ++i) s += expf(m[i] - M);
    red_sum[cell * 8 + ocg] = s;
    __syncthreads();

    if (ocg == 0) {
        float S = 0.0f;
#pragma unroll
        for (int i = 0; i < 8; ++i) S += red_sum[cell * 8 + i];
        float lse = M + logf(S);
        lse = fmaxf(lse, 0.0f);
        const int pd = tz * 4 + cz;
        const int ph = ty * 4 + cy;
        const int pw = tx * 4 + cx;
        out[((n * 24 + pd) * 24 + ph) * 24 + pw] = lse;
    }
}

extern "C" void kernel_launch(void* const* d_in, const int* in_sizes, int n_in,
                              void* d_out, int out_size)
{
    const float* x = (const float*)d_in[0];
    const float* w = (const float*)d_in[1];
    const float* b = (const float*)d_in[2];
    float* out = (float*)d_out;

    dim3 grid(216, 16);   // 6*6*6 conv tiles per batch, 16 batches
    fused_conv_pool_lse_kernel<<<grid, 512>>>(x, w, b, out);
}

// round 15
// speedup vs baseline: 1.1039x; 1.0008x over previous
#include <cuda_runtime.h>
#include <math.h>

// Fused: conv3d(32->64, k=3, pad=1) + bias + maxpool(2,2,2) + logsumexp(ch) + relu
// x: [16,32,48,48,48]  w: [64,32,3,3,3]  b: [64]  out: [16,1,24,24,24]
//
// Grid: (216 tiles, 16 batches). Block: 512 threads = 64 pooled cells x 8 oc-groups.
// Each CTA computes an 8x8x8 conv tile (=4x4x4 pooled cells), all 64 channels,
// looping over 32 input channels. Double-buffered smem staging: ic+1's halo and
// weights are prefetched into registers while ic computes, so LDG latency is
// hidden and only ONE __syncthreads per ic remains.
// Accumulation uses packed fp32x2 FMA (fma.rn.f32x2) over output-channel pairs.

#define IN_PY 12     // padded y-stride (floats)
#define IN_PZ 120    // padded z-stride (floats)
#define CH_STRIDE (48 * 48 * 48)

__global__ void __launch_bounds__(512, 1)
fused_conv_pool_lse_kernel(const float* __restrict__ x,
                           const float* __restrict__ w,
                           const float* __restrict__ b,
                           float* __restrict__ out)
{
    __shared__ __align__(16) float in_s[2][10 * IN_PZ];   // 10x10x10 halo, padded
    __shared__ __align__(16) float w_s[2][32 * 27 * 2];   // [oc_pair][k][half]
    __shared__ float b_s[64];
    __shared__ float red_max[64 * 8];
    __shared__ float red_sum[64 * 8];

    const int n  = blockIdx.y;
    const int t  = blockIdx.x;                 // 0..215
    const int tz = t / 36;
    const int ty = (t / 6) % 6;
    const int tx = t % 6;
    const int d0 = tz * 8, h0 = ty * 8, w0 = tx * 8;   // conv-tile origin

    const int tid  = threadIdx.x;
    const int cell = tid & 63;                 // pooled cell within 4x4x4
    const int ocg  = tid >> 6;                 // oc group 0..7 (8 oc each)
    const int cx = cell & 3, cy = (cell >> 2) & 3, cz = cell >> 4;

    if (tid < 64) b_s[tid] = b[tid];

    // ---- ic-invariant staging geometry (hoisted out of the main loop) ----
    // Input halo: element i covers idx = tid + i*512 (1000 total).
    int  xs_off[2];            // smem offset
    int  xg_off[2];            // gmem offset within one channel slab
    bool x_ok[2];              // in-bounds (else zero-fill)
    bool x_act[2];             // this thread participates
#pragma unroll
    for (int i = 0; i < 2; ++i) {
        int idx = tid + i * 512;
        x_act[i] = (idx < 1000);
        int zi  = idx / 100;
        int rem = idx - zi * 100;
        int yi  = rem / 10;
        int xi  = rem - yi * 10;
        int gz = d0 - 1 + zi, gy = h0 - 1 + yi, gx = w0 - 1 + xi;
        x_ok[i]   = ((unsigned)gz < 48u) & ((unsigned)gy < 48u) & ((unsigned)gx < 48u);
        xg_off[i] = (gz * 48 + gy) * 48 + gx;
        xs_off[i] = zi * IN_PZ + yi * IN_PY + xi;
    }
    // Weights: element j covers idx = tid + j*512 (1728 total), pair-interleaved smem.
    int  wg_off[4];
    int  ws_off[4];
    bool w_act[4];
#pragma unroll
    for (int j = 0; j < 4; ++j) {
        int idx = tid + j * 512;
        w_act[j] = (idx < 1728);
        int oc = idx / 27;
        int k  = idx - oc * 27;
        wg_off[j] = oc * (32 * 27) + k;                 // + ic*27 at load time
        ws_off[j] = ((oc >> 1) * 27 + k) * 2 + (oc & 1);
    }

    const float* xn = x + (size_t)n * 32 * CH_STRIDE;

    // ---- prefetch ic = 0 into registers ----
    float xr[2], wr[4];
#pragma unroll
    for (int i = 0; i < 2; ++i)
        xr[i] = (x_act[i] && x_ok[i]) ? __ldg(xn + xg_off[i]) : 0.0f;
#pragma unroll
    for (int j = 0; j < 4; ++j)
        wr[j] = w_act[j] ? __ldg(w + wg_off[j]) : 0.0f;

    // acc[pos][pair]: pos = dz*4+dy*2+dx over the 2x2x2 pooling window,
    // pair = packed (oc0, oc1) fp32x2 accumulator.
    unsigned long long acc[8][4];
#pragma unroll
    for (int i = 0; i < 8; ++i)
#pragma unroll
        for (int j = 0; j < 4; ++j) acc[i][j] = 0ull;

    for (int ic = 0; ic < 32; ++ic) {
        const int p = ic & 1;

        // ---- commit prefetched registers to smem buffer p ----
#pragma unroll
        for (int i = 0; i < 2; ++i)
            if (x_act[i]) in_s[p][xs_off[i]] = xr[i];
#pragma unroll
        for (int j = 0; j < 4; ++j)
            if (w_act[j]) w_s[p][ws_off[j]] = wr[j];
        __syncthreads();

        // ---- prefetch ic+1 (LDG in flight for the whole compute phase) ----
        if (ic < 31) {
            const float* xc = xn + (size_t)(ic + 1) * CH_STRIDE;
            const float* wc = w + (ic + 1) * 27;
#pragma unroll
            for (int i = 0; i < 2; ++i)
                xr[i] = (x_act[i] && x_ok[i]) ? __ldg(xc + xg_off[i]) : 0.0f;
#pragma unroll
            for (int j = 0; j < 4; ++j)
                wr[j] = w_act[j] ? __ldg(wc + wg_off[j]) : 0.0f;
        }

        // ---- accumulate from buffer p ----
        const float* inb = in_s[p] + (2 * cz) * IN_PZ + (2 * cy) * IN_PY + 2 * cx;
        const float* wb  = w_s[p] + (ocg * 4) * 27 * 2;

#pragma unroll
        for (int kz = 0; kz < 3; ++kz) {
#pragma unroll
            for (int ky = 0; ky < 3; ++ky) {
                // hoist weight pairs for kx = 0..2 (warp-uniform -> smem broadcast)
                unsigned long long wq[3][4];
#pragma unroll
                for (int kx = 0; kx < 3; ++kx) {
                    const int k = (kz * 3 + ky) * 3 + kx;
#pragma unroll
                    for (int pr = 0; pr < 4; ++pr)
                        wq[kx][pr] = *(const unsigned long long*)(wb + (pr * 27 + k) * 2);
                }
#pragma unroll
                for (int dz = 0; dz < 2; ++dz) {
#pragma unroll
                    for (int dy = 0; dy < 2; ++dy) {
                        const float* row = inb + (dz + kz) * IN_PZ + (dy + ky) * IN_PY;
                        // 4 consecutive x values cover all kx+dx combinations
                        float2 v01 = *(const float2*)(row);
                        float2 v23 = *(const float2*)(row + 2);
                        float vv[4];
                        vv[0] = v01.x; vv[1] = v01.y; vv[2] = v23.x; vv[3] = v23.y;
                        unsigned long long pdup[4];
#pragma unroll
                        for (int q = 0; q < 4; ++q)
                            asm("mov.b64 %0, {%1, %1};"
                                : "=l"(pdup[q]) : "r"(__float_as_uint(vv[q])));
#pragma unroll
                        for (int kx = 0; kx < 3; ++kx) {
#pragma unroll
                            for (int dx = 0; dx < 2; ++dx) {
                                const int pos = dz * 4 + dy * 2 + dx;
#pragma unroll
                                for (int pr = 0; pr < 4; ++pr)
                                    asm("fma.rn.f32x2 %0, %1, %2, %0;"
                                        : "+l"(acc[pos][pr])
                                        : "l"(pdup[kx + dx]), "l"(wq[kx][pr]));
                            }
                        }
                    }
                }
            }
        }
    }

    // ---- epilogue: bias + maxpool (in registers) ----
    float m[8];
#pragma unroll
    for (int pr = 0; pr < 4; ++pr) {
        float m0 = -INFINITY, m1 = -INFINITY;
#pragma unroll
        for (int pos = 0; pos < 8; ++pos) {
            unsigned int lo, hi;
            asm("mov.b64 {%0, %1}, %2;" : "=r"(lo), "=r"(hi) : "l"(acc[pos][pr]));
            m0 = fmaxf(m0, __uint_as_float(lo));
            m1 = fmaxf(m1, __uint_as_float(hi));
        }
        const int oc0 = ocg * 8 + pr * 2;
        m[pr * 2]     = m0 + b_s[oc0];
        m[pr * 2 + 1] = m1 + b_s[oc0 + 1];
    }
    float mx = m[0];
#pragma unroll
    for (int i = 1; i < 8; ++i) mx = fmaxf(mx, m[i]);

    // ---- logsumexp across the 8 oc-groups of this cell ----
    __syncthreads();
    red_max[cell * 8 + ocg] = mx;
    __syncthreads();

    float M = red_max[cell * 8 + 0];
#pragma unroll
    for (int i = 1; i < 8; ++i) M = fmaxf(M, red_max[cell * 8 + i]);

    float s = 0.0f;
#pragma unroll
    for (int i = 0; i < 8; ++i) s += expf(m[i] - M);
    red_sum[cell * 8 + ocg] = s;
    __syncthreads();

    if (ocg == 0) {
        float S = 0.0f;
#pragma unroll
        for (int i = 0; i < 8; ++i) S += red_sum[cell * 8 + i];
        float lse = M + logf(S);
        lse = fmaxf(lse, 0.0f);
        const int pd = tz * 4 + cz;
        const int ph = ty * 4 + cy;
        const int pw = tx * 4 + cx;
        out[((n * 24 + pd) * 24 + ph) * 24 + pw] = lse;
    }
}

extern "C" void kernel_launch(void* const* d_in, const int* in_sizes, int n_in,
                              void* d_out, int out_size)
{
    const float* x = (const float*)d_in[0];
    const float* w = (const float*)d_in[1];
    const float* b = (const float*)d_in[2];
    float* out = (float*)d_out;

    dim3 grid(216, 16);   // 6*6*6 conv tiles per batch, 16 batches
    fused_conv_pool_lse_kernel<<<grid, 512>>>(x, w, b, out);
}

// round 17
// speedup vs baseline: 1.7284x; 1.5656x over previous
#include <cuda_runtime.h>
#include <cuda_bf16.h>
#include <math.h>
#include <stdint.h>

// Fused conv3d(32->64,k=3,pad=1)+bias+maxpool2+LSE(ch)+ReLU.
// Two paths in one binary:
//   1) tcgen05 bf16x3 implicit-GEMM (only compiled in the arch-specific
//      sm_103a pass, gated on __CUDA_ARCH_FEAT_SM103_ALL so the plain
//      sm_103 pass still assembles).
//   2) proven fp32x2 scalar kernel (R15 winner) as fallback.
// Host dispatch: cudaFuncGetAttributes on the tensor kernel tells us whether
// the driver-selected cubin has a real body (regs >= 32) -> launch tensor,
// else launch scalar. Same answer every call => deterministic.

#if defined(__CUDA_ARCH__) && defined(__CUDA_ARCH_FEAT_SM103_ALL)
#define HAS_TCGEN05 1
#else
#define HAS_TCGEN05 0
#endif

// ======================= common helpers =======================
__device__ __forceinline__ uint32_t smem_u32(const void* p) {
    uint32_t a;
    asm("{ .reg .u64 t; cvta.to.shared.u64 t, %1; cvt.u32.u64 %0, t; }" : "=r"(a) : "l"(p));
    return a;
}

// ======================= weight pre-pack (plain ops, always compiled) ==========
__device__ uint32_t g_whi[27 * 1024];   // [tap][oc][icpair] bf16x2
__device__ uint32_t g_wlo[27 * 1024];

__global__ void pack_w_kernel(const float* __restrict__ w) {
    int e2 = blockIdx.x * 256 + threadIdx.x;          // 27*1024 = 27648
    if (e2 >= 27 * 1024) return;
    int tap = e2 >> 10;
    int oc  = (e2 >> 4) & 63;
    int icp = e2 & 15;
    int ic0 = icp * 2;
    float v0 = w[oc * 864 + ic0 * 27 + tap];
    float v1 = w[oc * 864 + (ic0 + 1) * 27 + tap];
    __nv_bfloat16 h0 = __float2bfloat16(v0);
    __nv_bfloat16 h1 = __float2bfloat16(v1);
    __nv_bfloat16 l0 = __float2bfloat16(v0 - __bfloat162float(h0));
    __nv_bfloat16 l1 = __float2bfloat16(v1 - __bfloat162float(h1));
    g_whi[e2] = ((uint32_t)__bfloat16_as_ushort(h1) << 16) | __bfloat16_as_ushort(h0);
    g_wlo[e2] = ((uint32_t)__bfloat16_as_ushort(l1) << 16) | __bfloat16_as_ushort(l0);
}

// ======================= tcgen05 path (sm_103a only) =======================
#define OFF_THI 1024
#define OFF_TLO 33792
#define OFF_A   66560
#define OFF_W   132096
#define SMEM_NEED 167936
#define offA(b, c) (OFF_A + (((b) << 1) | (c)) * 16384)
#define offW(b, c) (OFF_W + (((b) << 1) | (c)) * 8192)

#if HAS_TCGEN05
__device__ __forceinline__ uint32_t elect_one() {
    uint32_t p;
    asm volatile("{\n\t.reg .pred p;\n\telect.sync _|p, 0xFFFFFFFF;\n\tselp.b32 %0,1,0,p;\n\t}"
                 : "=r"(p));
    return p;
}
#define MBAR_INIT(a, c) asm volatile("mbarrier.init.shared.b64 [%0], %1;" ::"r"(a), "r"(c) : "memory")
#define MBAR_INVAL(a)   asm volatile("mbarrier.inval.shared.b64 [%0];" ::"r"(a) : "memory")
#define MBAR_WAIT(addr, parity) do {                                             \
    uint32_t _m = (addr), _p = (parity), _d;                                     \
    asm volatile("{\n\t.reg .pred p;\n\t"                                        \
        "mbarrier.try_wait.parity.acquire.cta.shared::cta.b64 p, [%1], %2;\n\t"  \
        "selp.b32 %0, 1, 0, p;\n\t}" : "=r"(_d) : "r"(_m), "r"(_p) : "memory");  \
    if (!_d) {                                                                   \
        asm volatile("{\n\t.reg .pred P1;\n\t"                                   \
            "W_%=:\n\t"                                                          \
            "mbarrier.try_wait.parity.acquire.cta.shared::cta.b64 P1, [%0], %1, 0x989680;\n\t" \
            "@P1 bra.uni D_%=;\n\t"                                              \
            "bra.uni W_%=;\n\t"                                                  \
            "D_%=:\n\t}" ::"r"(_m), "r"(_p) : "memory");                         \
    }                                                                            \
} while (0)
#define TC_ALLOC(sa, n)  asm volatile("tcgen05.alloc.cta_group::1.sync.aligned.shared::cta.b32 [%0], %1;" ::"r"(sa), "r"(n) : "memory")
#define TC_DEALLOC(t, n) asm volatile("tcgen05.dealloc.cta_group::1.sync.aligned.b32 %0, %1;" ::"r"(t), "r"(n))
#define TC_RELINQ()      asm volatile("tcgen05.relinquish_alloc_permit.cta_group::1.sync.aligned;")
#define TC_COMMIT(a)     asm volatile("tcgen05.commit.cta_group::1.mbarrier::arrive::one.shared::cluster.b64 [%0];" ::"r"(a) : "memory")
#define TC_WAIT_LD()     asm volatile("tcgen05.wait::ld.sync.aligned;" ::: "memory")
#define TC_FENCE_AFTER() asm volatile("tcgen05.fence::after_thread_sync;" ::: "memory")
#define TC_FENCE_BEFORE() asm volatile("tcgen05.fence::before_thread_sync;" ::: "memory")
#define FENCE_ASYNC()    asm volatile("fence.proxy.async.shared::cta;" ::: "memory")
#define SWZ128(o) ((o) ^ (((o) >> 3) & 0x70))

#define LDTM_X32(r, ta)                                                           \
    asm volatile("tcgen05.ld.sync.aligned.32x32b.x32.b32 "                        \
        "{%0, %1, %2, %3, %4, %5, %6, %7, %8, %9, %10, %11, %12, %13, %14, %15, " \
        " %16, %17, %18, %19, %20, %21, %22, %23, %24, %25, %26, %27, %28, %29, %30, %31}, [%32];" \
        : "=r"((r)[0]), "=r"((r)[1]), "=r"((r)[2]), "=r"((r)[3]),                 \
          "=r"((r)[4]), "=r"((r)[5]), "=r"((r)[6]), "=r"((r)[7]),                 \
          "=r"((r)[8]), "=r"((r)[9]), "=r"((r)[10]), "=r"((r)[11]),               \
          "=r"((r)[12]), "=r"((r)[13]), "=r"((r)[14]), "=r"((r)[15]),             \
          "=r"((r)[16]), "=r"((r)[17]), "=r"((r)[18]), "=r"((r)[19]),             \
          "=r"((r)[20]), "=r"((r)[21]), "=r"((r)[22]), "=r"((r)[23]),             \
          "=r"((r)[24]), "=r"((r)[25]), "=r"((r)[26]), "=r"((r)[27]),             \
          "=r"((r)[28]), "=r"((r)[29]), "=r"((r)[30]), "=r"((r)[31])              \
        : "r"(ta))

__device__ __forceinline__ uint64_t mk_desc(uint32_t addr) {
    const uint64_t base = (uint64_t(2) << 61) | (uint64_t(1) << 46) |
                          (uint64_t(64) << 32) | (uint64_t(1) << 16);
    return base | ((uint64_t)(addr >> 4) & 0x3FFF);
}
#define MMA_IDESC 0x08100490u   // F32 acc, bf16 x bf16, M=128, N=64
__device__ __forceinline__ void mma_bf16_ss(uint32_t d, uint64_t ad, uint64_t bd, uint32_t en) {
    asm volatile("{\n\t.reg .pred p;\n\tsetp.ne.u32 p, %5, 0;\n\t"
                 "tcgen05.mma.cta_group::1.kind::f16 [%0], %1, %2, %3, {%4, %4, %4, %4}, p;\n\t}"
                 :: "r"(d), "l"(ad), "l"(bd), "r"(MMA_IDESC), "r"(0u), "r"(en) : "memory");
}
#endif // HAS_TCGEN05

__global__ void __launch_bounds__(512, 1)
conv_mma_kernel(const float* __restrict__ x,
                const float* __restrict__ bias,
                float* __restrict__ out)
{
#if HAS_TCGEN05
    extern __shared__ char smem_raw[];
    uint32_t sb0 = smem_u32(smem_raw);
    uint32_t sb  = (sb0 + 1023u) & ~1023u;
    char* smemA  = smem_raw + (sb - sb0);

    const int tid = threadIdx.x;
    const int wid = tid >> 5;
    const int lid = tid & 31;

    const int n  = blockIdx.z;
    const int zp = blockIdx.y;
    const int ty = blockIdx.x / 6;
    const int tx = blockIdx.x % 6;

    if (wid == 0) TC_ALLOC(sb, 128);
    if (tid == 0) { MBAR_INIT(sb + 16, 1); MBAR_INIT(sb + 24, 1); }

    // ---- build T tile: bf16 hi/lo split, [4 z][10 y][10 x][40 ic-slots] ----
    {
        const float* xn = x + (size_t)n * 32 * 110592;
        __nv_bfloat16* Th = (__nv_bfloat16*)(smemA + OFF_THI);
        __nv_bfloat16* Tl = (__nv_bfloat16*)(smemA + OFF_TLO);
        const int gz0 = 2 * zp - 1, gy0 = 8 * ty - 1, gx0 = 8 * tx - 1;
#pragma unroll
        for (int it = 0; it < 25; ++it) {
            int e  = tid + it * 512;
            int ic = e / 400;
            int s  = e - ic * 400;
            int z  = s / 100;
            int r2 = s - z * 100;
            int y  = r2 / 10;
            int xx = r2 - y * 10;
            int gz = gz0 + z, gy = gy0 + y, gx = gx0 + xx;
            float v = 0.0f;
            if ((unsigned)gz < 48u && (unsigned)gy < 48u && (unsigned)gx < 48u)
                v = __ldg(xn + (size_t)ic * 110592 + (gz * 48 + gy) * 48 + gx);
            __nv_bfloat16 h = __float2bfloat16(v);
            int ti = ((z * 10 + y) * 10 + xx) * 40 + ic;
            Th[ti] = h;
            Tl[ti] = __float2bfloat16(v - __bfloat162float(h));
        }
    }
    __syncthreads();
    const uint32_t tmem = *(volatile uint32_t*)smemA;

    const int m  = tid >> 2;
    const int q  = tid & 3;
    const int dz = m >> 6, iy = (m >> 3) & 7, ix = m & 7;
    const uint32_t a_dst = SWZ128((uint32_t)(m * 128 + q * 16));

    int ph0 = 0, ph1 = 0;
    for (int tap = 0; tap < 27; ++tap) {
        const int kz = tap / 9, ky = (tap / 3) % 3, kx = tap % 3;
        const int bsel = tap & 1;

        if (tap >= 2) {
            if (bsel == 0) { MBAR_WAIT(sb + 16, ph0); ph0 ^= 1; }
            else           { MBAR_WAIT(sb + 24, ph1); ph1 ^= 1; }
        }

        // stage A (shifted im2col slice), hi + lo
        {
            uint32_t soff = (uint32_t)((((dz + kz) * 10 + iy + ky) * 10 + (ix + kx)) * 40 + q * 8) * 2u;
            uint4 vh = *(const uint4*)(smemA + OFF_THI + soff);
            uint4 vl = *(const uint4*)(smemA + OFF_TLO + soff);
            *(uint4*)(smemA + offA(bsel, 0) + a_dst) = vh;
            *(uint4*)(smemA + offA(bsel, 1) + a_dst) = vl;
        }
        // stage W (pre-packed), hi + lo
        {
            const uint32_t* whp = g_whi + tap * 1024;
            const uint32_t* wlp = g_wlo + tap * 1024;
#pragma unroll
            for (int r = 0; r < 2; ++r) {
                int j = tid + r * 512;
                uint32_t dst = SWZ128((uint32_t)((j >> 4) * 128 + (j & 15) * 4));
                *(uint32_t*)(smemA + offW(bsel, 0) + dst) = __ldg(whp + j);
                *(uint32_t*)(smemA + offW(bsel, 1) + dst) = __ldg(wlp + j);
            }
        }
        FENCE_ASYNC();
        __syncthreads();

        if (wid == 0 && elect_one()) {
            uint64_t adh = mk_desc(sb + offA(bsel, 0));
            uint64_t adl = mk_desc(sb + offA(bsel, 1));
            uint64_t bdh = mk_desc(sb + offW(bsel, 0));
            uint64_t bdl = mk_desc(sb + offW(bsel, 1));
            const uint32_t e0 = (tap == 0) ? 0u : 1u;
#pragma unroll
            for (int c = 0; c < 2; ++c) {
                mma_bf16_ss(tmem, adh + c * 2, bdh + c * 2, (c == 0) ? e0 : 1u);
                mma_bf16_ss(tmem, adh + c * 2, bdl + c * 2, 1u);
                mma_bf16_ss(tmem, adl + c * 2, bdh + c * 2, 1u);
            }
            TC_COMMIT(sb + 16 + bsel * 8);
        }
    }

    MBAR_WAIT(sb + 16, ph0);
    MBAR_WAIT(sb + 24, ph1);
    TC_FENCE_AFTER();

    // epilogue: TMEM -> smem (aliases A bufs)
    float* Dd = (float*)(smemA + OFF_A);
    if (wid < 4) {
        uint32_t dr[64];
        LDTM_X32(dr, tmem);
        LDTM_X32(dr + 32, tmem + 32);
        TC_WAIT_LD();
        TC_FENCE_BEFORE();
        float* row = Dd + (wid * 32 + lid) * 66;
#pragma unroll
        for (int c = 0; c < 64; ++c) row[c] = __uint_as_float(dr[c]);
    }
    __syncthreads();

    // pool + bias + LSE + ReLU: one warp per pooled cell
    {
        const int cell = tid >> 5;
        const int yy = cell >> 2, xx = cell & 3;
        const int oc0 = lid * 2;
        float v0 = -1e30f, v1 = -1e30f;
#pragma unroll
        for (int p8 = 0; p8 < 8; ++p8) {
            int dz2 = p8 >> 2, sy = (p8 >> 1) & 1, sx = p8 & 1;
            const float* rr = Dd + (dz2 * 64 + (yy * 2 + sy) * 8 + xx * 2 + sx) * 66;
            v0 = fmaxf(v0, rr[oc0]);
            v1 = fmaxf(v1, rr[oc0 + 1]);
        }
        v0 += __ldg(bias + oc0);
        v1 += __ldg(bias + oc0 + 1);
        float mx = fmaxf(v0, v1);
#pragma unroll
        for (int o = 16; o; o >>= 1) mx = fmaxf(mx, __shfl_xor_sync(0xffffffffu, mx, o));
        float s = expf(v0 - mx) + expf(v1 - mx);
#pragma unroll
        for (int o = 16; o; o >>= 1) s += __shfl_xor_sync(0xffffffffu, s, o);
        if (lid == 0) {
            float r = fmaxf(mx + logf(s), 0.0f);
            out[((n * 24 + zp) * 24 + (ty * 4 + yy)) * 24 + (tx * 4 + xx)] = r;
        }
    }

    __syncthreads();
    if (tid == 0) { MBAR_INVAL(sb + 16); MBAR_INVAL(sb + 24); }
    __syncthreads();
    if (wid == 0) { TC_RELINQ(); TC_DEALLOC(tmem, 128); }
#else
    // Empty body in non-sm_103a compilation passes; host dispatch detects this
    // via cudaFuncGetAttributes (tiny register count) and never launches it.
    (void)x; (void)bias; (void)out;
#endif
}

// ======================= scalar fallback (R15 winner, fp32x2 FMA) ==============
#define IN_PY 12
#define IN_PZ 120
#define CH_STRIDE (48 * 48 * 48)

__global__ void __launch_bounds__(512, 1)
fused_conv_pool_lse_kernel(const float* __restrict__ x,
                           const float* __restrict__ w,
                           const float* __restrict__ b,
                           float* __restrict__ out)
{
    __shared__ __align__(16) float in_s[2][10 * IN_PZ];
    __shared__ __align__(16) float w_s[2][32 * 27 * 2];
    __shared__ float b_s[64];
    __shared__ float red_max[64 * 8];
    __shared__ float red_sum[64 * 8];

    const int n  = blockIdx.y;
    const int t  = blockIdx.x;
    const int tz = t / 36;
    const int ty = (t / 6) % 6;
    const int tx = t % 6;
    const int d0 = tz * 8, h0 = ty * 8, w0 = tx * 8;

    const int tid  = threadIdx.x;
    const int cell = tid & 63;
    const int ocg  = tid >> 6;
    const int cx = cell & 3, cy = (cell >> 2) & 3, cz = cell >> 4;

    if (tid < 64) b_s[tid] = b[tid];

    int  xs_off[2];
    int  xg_off[2];
    bool x_ok[2];
    bool x_act[2];
#pragma unroll
    for (int i = 0; i < 2; ++i) {
        int idx = tid + i * 512;
        x_act[i] = (idx < 1000);
        int zi  = idx / 100;
        int rem = idx - zi * 100;
        int yi  = rem / 10;
        int xi  = rem - yi * 10;
        int gz = d0 - 1 + zi, gy = h0 - 1 + yi, gx = w0 - 1 + xi;
        x_ok[i]   = ((unsigned)gz < 48u) & ((unsigned)gy < 48u) & ((unsigned)gx < 48u);
        xg_off[i] = (gz * 48 + gy) * 48 + gx;
        xs_off[i] = zi * IN_PZ + yi * IN_PY + xi;
    }
    int  wg_off[4];
    int  ws_off[4];
    bool w_act[4];
#pragma unroll
    for (int j = 0; j < 4; ++j) {
        int idx = tid + j * 512;
        w_act[j] = (idx < 1728);
        int oc = idx / 27;
        int k  = idx - oc * 27;
        wg_off[j] = oc * (32 * 27) + k;
        ws_off[j] = ((oc >> 1) * 27 + k) * 2 + (oc & 1);
    }

    const float* xn = x + (size_t)n * 32 * CH_STRIDE;

    float xr[2], wr[4];
#pragma unroll
    for (int i = 0; i < 2; ++i)
        xr[i] = (x_act[i] && x_ok[i]) ? __ldg(xn + xg_off[i]) : 0.0f;
#pragma unroll
    for (int j = 0; j < 4; ++j)
        wr[j] = w_act[j] ? __ldg(w + wg_off[j]) : 0.0f;

    unsigned long long acc[8][4];
#pragma unroll
    for (int i = 0; i < 8; ++i)
#pragma unroll
        for (int j = 0; j < 4; ++j) acc[i][j] = 0ull;

    for (int ic = 0; ic < 32; ++ic) {
        const int p = ic & 1;
#pragma unroll
        for (int i = 0; i < 2; ++i)
            if (x_act[i]) in_s[p][xs_off[i]] = xr[i];
#pragma unroll
        for (int j = 0; j < 4; ++j)
            if (w_act[j]) w_s[p][ws_off[j]] = wr[j];
        __syncthreads();

        if (ic < 31) {
            const float* xc = xn + (size_t)(ic + 1) * CH_STRIDE;
            const float* wc = w + (ic + 1) * 27;
#pragma unroll
            for (int i = 0; i < 2; ++i)
                xr[i] = (x_act[i] && x_ok[i]) ? __ldg(xc + xg_off[i]) : 0.0f;
#pragma unroll
            for (int j = 0; j < 4; ++j)
                wr[j] = w_act[j] ? __ldg(wc + wg_off[j]) : 0.0f;
        }

        const float* inb = in_s[p] + (2 * cz) * IN_PZ + (2 * cy) * IN_PY + 2 * cx;
        const float* wb  = w_s[p] + (ocg * 4) * 27 * 2;

#pragma unroll
        for (int kz = 0; kz < 3; ++kz) {
#pragma unroll
            for (int ky = 0; ky < 3; ++ky) {
                unsigned long long wq[3][4];
#pragma unroll
                for (int kx = 0; kx < 3; ++kx) {
                    const int k = (kz * 3 + ky) * 3 + kx;
#pragma unroll
                    for (int pr = 0; pr < 4; ++pr)
                        wq[kx][pr] = *(const unsigned long long*)(wb + (pr * 27 + k) * 2);
                }
#pragma unroll
                for (int dz = 0; dz < 2; ++dz) {
#pragma unroll
                    for (int dy = 0; dy < 2; ++dy) {
                        const float* row = inb + (dz + kz) * IN_PZ + (dy + ky) * IN_PY;
                        float2 v01 = *(const float2*)(row);
                        float2 v23 = *(const float2*)(row + 2);
                        float vv[4];
                        vv[0] = v01.x; vv[1] = v01.y; vv[2] = v23.x; vv[3] = v23.y;
                        unsigned long long pdup[4];
#pragma unroll
                        for (int q = 0; q < 4; ++q)
                            asm("mov.b64 %0, {%1, %1};"
                                : "=l"(pdup[q]) : "r"(__float_as_uint(vv[q])));
#pragma unroll
                        for (int kx = 0; kx < 3; ++kx) {
#pragma unroll
                            for (int dx = 0; dx < 2; ++dx) {
                                const int pos = dz * 4 + dy * 2 + dx;
#pragma unroll
                                for (int pr = 0; pr < 4; ++pr)
                                    asm("fma.rn.f32x2 %0, %1, %2, %0;"
                                        : "+l"(acc[pos][pr])
                                        : "l"(pdup[kx + dx]), "l"(wq[kx][pr]));
                            }
                        }
                    }
                }
            }
        }
    }

    float m[8];
#pragma unroll
    for (int pr = 0; pr < 4; ++pr) {
        float m0 = -INFINITY, m1 = -INFINITY;
#pragma unroll
        for (int pos = 0; pos < 8; ++pos) {
            unsigned int lo, hi;
            asm("mov.b64 {%0, %1}, %2;" : "=r"(lo), "=r"(hi) : "l"(acc[pos][pr]));
            m0 = fmaxf(m0, __uint_as_float(lo));
            m1 = fmaxf(m1, __uint_as_float(hi));
        }
        const int oc0 = ocg * 8 + pr * 2;
        m[pr * 2]     = m0 + b_s[oc0];
        m[pr * 2 + 1] = m1 + b_s[oc0 + 1];
    }
    float mx = m[0];
#pragma unroll
    for (int i = 1; i < 8; ++i) mx = fmaxf(mx, m[i]);

    __syncthreads();
    red_max[cell * 8 + ocg] = mx;
    __syncthreads();

    float M = red_max[cell * 8 + 0];
#pragma unroll
    for (int i = 1; i < 8; ++i) M = fmaxf(M, red_max[cell * 8 + i]);

    float s = 0.0f;
#pragma unroll
    for (int i = 0; i < 8; ++i) s += expf(m[i] - M);
    red_sum[cell * 8 + ocg] = s;
    __syncthreads();

    if (ocg == 0) {
        float S = 0.0f;
#pragma unroll
        for (int i = 0; i < 8; ++i) S += red_sum[cell * 8 + i];
        float lse = M + logf(S);
        lse = fmaxf(lse, 0.0f);
        const int pd = tz * 4 + cz;
        const int ph = ty * 4 + cy;
        const int pw = tx * 4 + cx;
        out[((n * 24 + pd) * 24 + ph) * 24 + pw] = lse;
    }
}

// ======================= host dispatch =======================
extern "C" void kernel_launch(void* const* d_in, const int* in_sizes, int n_in,
                              void* d_out, int out_size)
{
    const float* x = (const float*)d_in[0];
    const float* w = (const float*)d_in[1];
    const float* b = (const float*)d_in[2];
    float* out = (float*)d_out;

    // Does the driver-selected cubin contain a real tcgen05 body?
    // (Empty guarded body => tiny register count.) Pure host query: capture-safe,
    // same result on every call.
    bool use_tensor = false;
    cudaFuncAttributes attr;
    if (cudaFuncGetAttributes(&attr, conv_mma_kernel) == cudaSuccess)
        use_tensor = (attr.numRegs >= 32);

    if (use_tensor) {
        (void)cudaFuncSetAttribute(conv_mma_kernel,
                                   cudaFuncAttributeMaxDynamicSharedMemorySize, SMEM_NEED);
        pack_w_kernel<<<(27 * 1024 + 255) / 256, 256>>>(w);
        dim3 grid(36, 24, 16);
        conv_mma_kernel<<<grid, 512, SMEM_NEED>>>(x, b, out);
    } else {
        dim3 grid(216, 16);
        fused_conv_pool_lse_kernel<<<grid, 512>>>(x, w, b, out);
    }
}